// round 9
// baseline (speedup 1.0000x reference)
#include <cuda_runtime.h>
#include <cuda_fp16.h>
#include <cstdint>

// SparseChannelLinear: gather(cols)+fp16 -> fp16 mma.sync m16n8k16 GEMM
// (fragment-packed operands, 64x64 warp tile, reg-double-buffered) ->
// scatter(rows)+bias.

#define ALPHA_S 0.05f

static constexpr int MT   = 8192;
static constexpr int KC   = 2048;
static constexpr int NR   = 2048;
static constexpr int FIN  = 4096;
static constexpr int FOUT = 4096;

static constexpr int BM = 128, BN = 128, BK = 64;   // BK elements (4 k16-atoms)
static constexpr int STAGES  = 3;
static constexpr int KTILES  = KC / BK;             // 32
static constexpr int THREADS = 128;                 // 4 warps, 2x2 of 64x64 tiles

static constexpr int K16S = KC / 16;                // 128 k16-atoms total

// smem: rows cache, bias cache, then 3 stages of (A 16K + B 16K)
static constexpr int OFF_ROWS    = 0;      // 128 x int
static constexpr int OFF_BIAS    = 512;    // 128 x float
static constexpr int OFF_TILES   = 1024;
static constexpr int A_BYTES     = BM * BK * 2;           // 16384
static constexpr int STAGE_BYTES = 2 * A_BYTES;           // 32768
static constexpr int SMEM_TOTAL  = OFF_TILES + STAGES * STAGE_BYTES;  // 99328

// scratch, fragment-packed for mma.m16n8k16.f16 (layouts proven in round 8):
__device__ uint4 g_xc[(size_t)(MT / 16) * K16S * 32];
__device__ uint2 g_wt[(size_t)(NR / 8) * K16S * 32];

// ---------------------------------------------------------------------------
__device__ __forceinline__ uint32_t smem_to_u32(const void* p) {
    uint32_t a;
    asm("{ .reg .u64 t; cvta.to.shared.u64 t, %1; cvt.u32.u64 %0, t; }" : "=r"(a) : "l"(p));
    return a;
}
__device__ __forceinline__ uint32_t pack_h2(float lo, float hi) {
    __half2 h = __floats2half2_rn(lo, hi);
    return *reinterpret_cast<uint32_t*>(&h);
}
#define CP_ASYNC16(dst, src) \
    asm volatile("cp.async.cg.shared.global [%0], [%1], 16;" :: "r"(dst), "l"(src))
#define CP_COMMIT() asm volatile("cp.async.commit_group;" ::: "memory")
#define CP_WAIT1()  asm volatile("cp.async.wait_group 1;" ::: "memory")

#define LDS128(r, addr) \
    asm volatile("ld.shared.v4.b32 {%0,%1,%2,%3}, [%4];" \
        : "=r"((r)[0]), "=r"((r)[1]), "=r"((r)[2]), "=r"((r)[3]) : "r"(addr))
#define LDS64(r, addr) \
    asm volatile("ld.shared.v2.b32 {%0,%1}, [%2];" \
        : "=r"((r)[0]), "=r"((r)[1]) : "r"(addr))

__device__ __forceinline__ void mma_f16(float* c, const uint32_t* a, const uint32_t* b) {
    asm volatile(
        "mma.sync.aligned.m16n8k16.row.col.f32.f16.f16.f32 "
        "{%0,%1,%2,%3}, {%4,%5,%6,%7}, {%8,%9}, {%0,%1,%2,%3};"
        : "+f"(c[0]), "+f"(c[1]), "+f"(c[2]), "+f"(c[3])
        : "r"(a[0]), "r"(a[1]), "r"(a[2]), "r"(a[3]), "r"(b[0]), "r"(b[1]));
}

// ---------------------------------------------------------------------------
// Kernel 1: gather active input channels into fp16 A-fragment-packed layout.
__global__ void gather_kernel(const float* __restrict__ x,
                              const int* __restrict__ cols) {
    int t = blockIdx.x * blockDim.x + threadIdx.x;
    int lane   = t & 31;
    int k16    = (t >> 5) & (K16S - 1);
    int m_atom = t >> 12;
    int lr = lane >> 2, lc = lane & 3;
    const int* cb = cols + k16 * 16;
    int c0 = __ldg(cb + 2 * lc);
    int c1 = __ldg(cb + 2 * lc + 1);
    int c2 = __ldg(cb + 2 * lc + 8);
    int c3 = __ldg(cb + 2 * lc + 9);
    const float* r1 = x + (size_t)(m_atom * 16 + lr) * FIN;
    const float* r2 = r1 + (size_t)8 * FIN;
    uint4 o;
    o.x = pack_h2(__ldg(r1 + c0), __ldg(r1 + c1));
    o.y = pack_h2(__ldg(r2 + c0), __ldg(r2 + c1));
    o.z = pack_h2(__ldg(r1 + c2), __ldg(r1 + c3));
    o.w = pack_h2(__ldg(r2 + c2), __ldg(r2 + c3));
    g_xc[t] = o;
}

// Kernel 1b: weights -> alpha-folded fp16, B-fragment-packed layout.
__global__ void wconv_kernel(const float* __restrict__ w) {
    int t = blockIdx.x * blockDim.x + threadIdx.x;
    int lane   = t & 31;
    int k16    = (t >> 5) & (K16S - 1);
    int n_atom = t >> 12;
    const float* wr = w + (size_t)(n_atom * 8 + (lane >> 2)) * KC
                        + k16 * 16 + 2 * (lane & 3);
    uint2 o;
    o.x = pack_h2(__ldg(wr)     * ALPHA_S, __ldg(wr + 1) * ALPHA_S);
    o.y = pack_h2(__ldg(wr + 8) * ALPHA_S, __ldg(wr + 9) * ALPHA_S);
    g_wt[t] = o;
}

// Kernel 2: out = broadcast(bias) everywhere (inactive rows keep it).
__global__ void biasfill_kernel(float4* __restrict__ out,
                                const float4* __restrict__ bias) {
    int i = blockIdx.x * blockDim.x + threadIdx.x;
    out[i] = bias[i & (FOUT / 4 - 1)];
}

// ---------------------------------------------------------------------------
// Kernel 3: fp16 mma.sync GEMM. 4 warps (2m x 2n), warp tile 64x64,
// fragment-packed smem, 3-stage cp.async pipeline, register double-buffered
// fragments, single barrier per k-tile.
__global__ __launch_bounds__(THREADS, 2) void gemm_kernel(
    const float* __restrict__ bias,
    const int* __restrict__ rows,
    float* __restrict__ out)
{
    extern __shared__ char smem[];
    const uint32_t sbase = smem_to_u32(smem);
    const int tid = threadIdx.x;
    const int wid = tid >> 5;
    const int lid = tid & 31;
    const int n0 = blockIdx.x * BN;
    const int m0 = blockIdx.y * BM;

    int*   srows = (int*)(smem + OFF_ROWS);
    float* sbias = (float*)(smem + OFF_BIAS);
    {
        int r = __ldg(&rows[n0 + tid]);
        srows[tid] = r;
        sbias[tid] = __ldg(&bias[r]);
    }

    // stage fill: 2048 16B chunks (A:1024 then B:1024), 16 per thread.
    auto refill = [&](int kt, int s) {
        const uint32_t stg = sbase + OFF_TILES + s * STAGE_BYTES;
        #pragma unroll
        for (int i = 0; i < 16; ++i) {
            int c = tid + i * THREADS;
            uint32_t dst = stg + c * 16;
            const void* src;
            if (c < 1024) {                 // A: atom = m_atom_l*4 + k16_l
                int atom = c >> 5, lane = c & 31;
                int m_atom_g = (m0 >> 4) + (atom >> 2);
                int k16_g    = kt * 4 + (atom & 3);
                src = (const void*)(g_xc + ((size_t)m_atom_g * K16S + k16_g) * 32 + lane);
            } else {                        // B: atom = n_atom_l*4 + k16_l
                int cc = c - 1024;
                int atom = cc >> 4, pair = cc & 15;
                int n_atom_g = (n0 >> 3) + (atom >> 2);
                int k16_g    = kt * 4 + (atom & 3);
                src = (const void*)((const uint4*)g_wt +
                      ((size_t)n_atom_g * K16S + k16_g) * 16 + pair);
            }
            CP_ASYNC16(dst, src);
        }
    };

    refill(0, 0); CP_COMMIT();
    refill(1, 1); CP_COMMIT();

    const int ma = (wid & 1) * 4;    // warp m-atom base (4 atoms = 64 rows)
    const int nb = (wid >> 1) * 8;   // warp n-atom base (8 atoms = 64 cols)

    float acc[4][8][4];
    #pragma unroll
    for (int mt = 0; mt < 4; ++mt)
        #pragma unroll
        for (int nt = 0; nt < 8; ++nt)
            #pragma unroll
            for (int i = 0; i < 4; ++i) acc[mt][nt][i] = 0.f;

    uint32_t a[2][4][4], b[2][8][2];

    for (int kt = 0; kt < KTILES; ++kt) {
        const int s = kt % STAGES;
        CP_WAIT1();
        // This barrier both publishes stage s (all threads' cp.async done) and
        // orders every warp's reads of stage (kt)%3 from the PREVIOUS iteration
        // before the refill below overwrites it -> no trailing barrier needed.
        __syncthreads();
        if (kt + 2 < KTILES) refill(kt + 2, (kt + 2) % STAGES);
        CP_COMMIT();

        const uint32_t stg = sbase + OFF_TILES + s * STAGE_BYTES;
        const uint32_t aW  = stg + lid * 16;            // + atom*512
        const uint32_t bW  = stg + A_BYTES + lid * 8;   // + atom*256

        // prime k16=0 fragments
        #pragma unroll
        for (int mt = 0; mt < 4; ++mt)
            LDS128(a[0][mt], aW + ((ma + mt) * 4) * 512);
        #pragma unroll
        for (int nt = 0; nt < 8; ++nt)
            LDS64(b[0][nt], bW + ((nb + nt) * 4) * 256);

        #pragma unroll
        for (int k16 = 0; k16 < 4; ++k16) {
            const int cur = k16 & 1, nxt = cur ^ 1;
            if (k16 < 3) {   // prefetch next step's fragments during MMAs
                #pragma unroll
                for (int mt = 0; mt < 4; ++mt)
                    LDS128(a[nxt][mt], aW + ((ma + mt) * 4 + k16 + 1) * 512);
                #pragma unroll
                for (int nt = 0; nt < 8; ++nt)
                    LDS64(b[nxt][nt], bW + ((nb + nt) * 4 + k16 + 1) * 256);
            }
            #pragma unroll
            for (int mt = 0; mt < 4; ++mt)
                #pragma unroll
                for (int nt = 0; nt < 8; ++nt)
                    mma_f16(acc[mt][nt], a[cur][mt], b[cur][nt]);
        }
    }

    // epilogue: scatter acc + bias to active output channels (alpha in W)
    const int lr = lid >> 2;
    const int lc = lid & 3;
    #pragma unroll
    for (int mt = 0; mt < 4; ++mt) {
        int mA = m0 + (ma + mt) * 16 + lr;
        float* rowA = out + (size_t)mA * FOUT;
        float* rowB = rowA + (size_t)8 * FOUT;
        #pragma unroll
        for (int nt = 0; nt < 8; ++nt) {
            int nloc = (nb + nt) * 8 + lc * 2;
            int r0 = srows[nloc], r1 = srows[nloc + 1];
            float b0 = sbias[nloc], b1 = sbias[nloc + 1];
            rowA[r0] = acc[mt][nt][0] + b0;
            rowA[r1] = acc[mt][nt][1] + b1;
            rowB[r0] = acc[mt][nt][2] + b0;
            rowB[r1] = acc[mt][nt][3] + b1;
        }
    }
}

// ---------------------------------------------------------------------------
extern "C" void kernel_launch(void* const* d_in, const int* in_sizes, int n_in,
                              void* d_out, int out_size) {
    const float* x    = (const float*)d_in[0];
    const float* w    = (const float*)d_in[1];
    const float* bias = (const float*)d_in[2];
    const int*   rows = (const int*)d_in[3];
    const int*   cols = (const int*)d_in[4];
    float*       out  = (float*)d_out;

    cudaFuncSetAttribute(gemm_kernel, cudaFuncAttributeMaxDynamicSharedMemorySize,
                         SMEM_TOTAL);

    gather_kernel<<<(MT / 16) * K16S * 32 / 256, 256>>>(x, cols);
    wconv_kernel<<<(NR / 8) * K16S * 32 / 256, 256>>>(w);
    biasfill_kernel<<<((size_t)MT * FOUT / 4) / 256, 256>>>((float4*)d_out,
                                                            (const float4*)bias);
    gemm_kernel<<<dim3(NR / BN, MT / BM), THREADS, SMEM_TOTAL>>>(bias, rows, out);
}

// round 10
// speedup vs baseline: 1.0660x; 1.0660x over previous
#include <cuda_runtime.h>
#include <cuda_fp16.h>
#include <cstdint>

// SparseChannelLinear: gather(cols)+fp16 -> fp16 mma.sync m16n8k16 GEMM
// (fragment-packed operands, 8 warps x 64x32 tiles for occupancy) ->
// scatter(rows)+bias.

#define ALPHA_S 0.05f

static constexpr int MT   = 8192;
static constexpr int KC   = 2048;
static constexpr int NR   = 2048;
static constexpr int FIN  = 4096;
static constexpr int FOUT = 4096;

static constexpr int BM = 128, BN = 128, BK = 64;   // BK elements (4 k16-atoms)
static constexpr int STAGES  = 3;
static constexpr int KTILES  = KC / BK;             // 32
static constexpr int THREADS = 256;                 // 8 warps, 2m x 4n of 64x32

static constexpr int K16S = KC / 16;                // 128 k16-atoms total

// smem: rows cache, bias cache, then 3 stages of (A 16K + B 16K)
static constexpr int OFF_ROWS    = 0;      // 128 x int
static constexpr int OFF_BIAS    = 512;    // 128 x float
static constexpr int OFF_TILES   = 1024;
static constexpr int A_BYTES     = BM * BK * 2;           // 16384
static constexpr int STAGE_BYTES = 2 * A_BYTES;           // 32768
static constexpr int SMEM_TOTAL  = OFF_TILES + STAGES * STAGE_BYTES;  // 99328

// scratch, fragment-packed for mma.m16n8k16.f16 (layouts proven in round 8):
// g_xc: [m_atom(512)][k16(128)][lane(32)] x uint4  (A regs a0..a3)
// g_wt: [n_atom(256)][k16(128)][lane(32)] x uint2  (B regs b0..b1, alpha-folded)
__device__ uint4 g_xc[(size_t)(MT / 16) * K16S * 32];
__device__ uint2 g_wt[(size_t)(NR / 8) * K16S * 32];

// ---------------------------------------------------------------------------
__device__ __forceinline__ uint32_t smem_to_u32(const void* p) {
    uint32_t a;
    asm("{ .reg .u64 t; cvta.to.shared.u64 t, %1; cvt.u32.u64 %0, t; }" : "=r"(a) : "l"(p));
    return a;
}
__device__ __forceinline__ uint32_t pack_h2(float lo, float hi) {
    __half2 h = __floats2half2_rn(lo, hi);
    return *reinterpret_cast<uint32_t*>(&h);
}
#define CP_ASYNC16(dst, src) \
    asm volatile("cp.async.cg.shared.global [%0], [%1], 16;" :: "r"(dst), "l"(src))
#define CP_COMMIT() asm volatile("cp.async.commit_group;" ::: "memory")
#define CP_WAIT1()  asm volatile("cp.async.wait_group 1;" ::: "memory")

#define LDS128(r, addr) \
    asm volatile("ld.shared.v4.b32 {%0,%1,%2,%3}, [%4];" \
        : "=r"((r)[0]), "=r"((r)[1]), "=r"((r)[2]), "=r"((r)[3]) : "r"(addr))
#define LDS64(r, addr) \
    asm volatile("ld.shared.v2.b32 {%0,%1}, [%2];" \
        : "=r"((r)[0]), "=r"((r)[1]) : "r"(addr))

__device__ __forceinline__ void mma_f16(float* c, const uint32_t* a, const uint32_t* b) {
    asm volatile(
        "mma.sync.aligned.m16n8k16.row.col.f32.f16.f16.f32 "
        "{%0,%1,%2,%3}, {%4,%5,%6,%7}, {%8,%9}, {%0,%1,%2,%3};"
        : "+f"(c[0]), "+f"(c[1]), "+f"(c[2]), "+f"(c[3])
        : "r"(a[0]), "r"(a[1]), "r"(a[2]), "r"(a[3]), "r"(b[0]), "r"(b[1]));
}

// ---------------------------------------------------------------------------
// Kernel 1: gather active input channels into fp16 A-fragment-packed layout.
__global__ void gather_kernel(const float* __restrict__ x,
                              const int* __restrict__ cols) {
    int t = blockIdx.x * blockDim.x + threadIdx.x;
    int lane   = t & 31;
    int k16    = (t >> 5) & (K16S - 1);
    int m_atom = t >> 12;
    int lr = lane >> 2, lc = lane & 3;
    const int* cb = cols + k16 * 16;
    int c0 = __ldg(cb + 2 * lc);
    int c1 = __ldg(cb + 2 * lc + 1);
    int c2 = __ldg(cb + 2 * lc + 8);
    int c3 = __ldg(cb + 2 * lc + 9);
    const float* r1 = x + (size_t)(m_atom * 16 + lr) * FIN;
    const float* r2 = r1 + (size_t)8 * FIN;
    uint4 o;
    o.x = pack_h2(__ldg(r1 + c0), __ldg(r1 + c1));
    o.y = pack_h2(__ldg(r2 + c0), __ldg(r2 + c1));
    o.z = pack_h2(__ldg(r1 + c2), __ldg(r1 + c3));
    o.w = pack_h2(__ldg(r2 + c2), __ldg(r2 + c3));
    g_xc[t] = o;
}

// Kernel 1b: weights -> alpha-folded fp16, B-fragment-packed layout.
__global__ void wconv_kernel(const float* __restrict__ w) {
    int t = blockIdx.x * blockDim.x + threadIdx.x;
    int lane   = t & 31;
    int k16    = (t >> 5) & (K16S - 1);
    int n_atom = t >> 12;
    const float* wr = w + (size_t)(n_atom * 8 + (lane >> 2)) * KC
                        + k16 * 16 + 2 * (lane & 3);
    uint2 o;
    o.x = pack_h2(__ldg(wr)     * ALPHA_S, __ldg(wr + 1) * ALPHA_S);
    o.y = pack_h2(__ldg(wr + 8) * ALPHA_S, __ldg(wr + 9) * ALPHA_S);
    g_wt[t] = o;
}

// Kernel 2: out = broadcast(bias) everywhere (inactive rows keep it).
__global__ void biasfill_kernel(float4* __restrict__ out,
                                const float4* __restrict__ bias) {
    int i = blockIdx.x * blockDim.x + threadIdx.x;
    out[i] = bias[i & (FOUT / 4 - 1)];
}

// ---------------------------------------------------------------------------
// Kernel 3: fp16 mma.sync GEMM. 8 warps (2m x 4n), warp tile 64x32,
// fragment-packed smem, 3-stage cp.async pipeline, one barrier per k-tile.
// 2 CTAs/SM (16 warps/SM) for latency hiding; acc=64 regs/thread.
__global__ __launch_bounds__(THREADS, 2) void gemm_kernel(
    const float* __restrict__ bias,
    const int* __restrict__ rows,
    float* __restrict__ out)
{
    extern __shared__ char smem[];
    const uint32_t sbase = smem_to_u32(smem);
    const int tid = threadIdx.x;
    const int wid = tid >> 5;
    const int lid = tid & 31;
    const int n0 = blockIdx.x * BN;
    const int m0 = blockIdx.y * BM;

    int*   srows = (int*)(smem + OFF_ROWS);
    float* sbias = (float*)(smem + OFF_BIAS);
    if (tid < 128) {
        int r = __ldg(&rows[n0 + tid]);
        srows[tid] = r;
        sbias[tid] = __ldg(&bias[r]);
    }

    // stage fill: 2048 16B chunks (A:1024 then B:1024), 8 per thread.
    auto refill = [&](int kt, int s) {
        const uint32_t stg = sbase + OFF_TILES + s * STAGE_BYTES;
        #pragma unroll
        for (int i = 0; i < 8; ++i) {
            int c = tid + i * THREADS;
            uint32_t dst = stg + c * 16;
            const void* src;
            if (c < 1024) {                 // A: atom = m_atom_l*4 + k16_l
                int atom = c >> 5, lane = c & 31;
                int m_atom_g = (m0 >> 4) + (atom >> 2);
                int k16_g    = kt * 4 + (atom & 3);
                src = (const void*)(g_xc + ((size_t)m_atom_g * K16S + k16_g) * 32 + lane);
            } else {                        // B: atom = n_atom_l*4 + k16_l
                int cc = c - 1024;
                int atom = cc >> 4, pair = cc & 15;
                int n_atom_g = (n0 >> 3) + (atom >> 2);
                int k16_g    = kt * 4 + (atom & 3);
                src = (const void*)((const uint4*)g_wt +
                      ((size_t)n_atom_g * K16S + k16_g) * 16 + pair);
            }
            CP_ASYNC16(dst, src);
        }
    };

    refill(0, 0); CP_COMMIT();
    refill(1, 1); CP_COMMIT();

    const int ma = (wid & 1) * 4;    // warp m-atom base (4 atoms = 64 rows)
    const int nb = (wid >> 1) * 4;   // warp n-atom base (4 atoms = 32 cols)

    float acc[4][4][4];
    #pragma unroll
    for (int mt = 0; mt < 4; ++mt)
        #pragma unroll
        for (int nt = 0; nt < 4; ++nt)
            #pragma unroll
            for (int i = 0; i < 4; ++i) acc[mt][nt][i] = 0.f;

    for (int kt = 0; kt < KTILES; ++kt) {
        const int s = kt % STAGES;
        CP_WAIT1();
        // publishes stage s AND orders prior reads of the stage about to be
        // refilled -> single barrier per k-tile.
        __syncthreads();
        if (kt + 2 < KTILES) refill(kt + 2, (kt + 2) % STAGES);
        CP_COMMIT();

        const uint32_t stg = sbase + OFF_TILES + s * STAGE_BYTES;
        const uint32_t aW  = stg + lid * 16;            // + atom*512
        const uint32_t bW  = stg + A_BYTES + lid * 8;   // + atom*256

        #pragma unroll
        for (int k16 = 0; k16 < 4; ++k16) {
            uint32_t a[4][4], b[4][2];
            #pragma unroll
            for (int mt = 0; mt < 4; ++mt)
                LDS128(a[mt], aW + ((ma + mt) * 4 + k16) * 512);
            #pragma unroll
            for (int nt = 0; nt < 4; ++nt)
                LDS64(b[nt], bW + ((nb + nt) * 4 + k16) * 256);
            #pragma unroll
            for (int mt = 0; mt < 4; ++mt)
                #pragma unroll
                for (int nt = 0; nt < 4; ++nt)
                    mma_f16(acc[mt][nt], a[mt], b[nt]);
        }
    }

    // epilogue: scatter acc + bias to active output channels (alpha in W)
    const int lr = lid >> 2;
    const int lc = lid & 3;
    #pragma unroll
    for (int mt = 0; mt < 4; ++mt) {
        int mA = m0 + (ma + mt) * 16 + lr;
        float* rowA = out + (size_t)mA * FOUT;
        float* rowB = rowA + (size_t)8 * FOUT;
        #pragma unroll
        for (int nt = 0; nt < 4; ++nt) {
            int nloc = (nb + nt) * 8 + lc * 2;
            int r0 = srows[nloc], r1 = srows[nloc + 1];
            float b0 = sbias[nloc], b1 = sbias[nloc + 1];
            rowA[r0] = acc[mt][nt][0] + b0;
            rowA[r1] = acc[mt][nt][1] + b1;
            rowB[r0] = acc[mt][nt][2] + b0;
            rowB[r1] = acc[mt][nt][3] + b1;
        }
    }
}

// ---------------------------------------------------------------------------
extern "C" void kernel_launch(void* const* d_in, const int* in_sizes, int n_in,
                              void* d_out, int out_size) {
    const float* x    = (const float*)d_in[0];
    const float* w    = (const float*)d_in[1];
    const float* bias = (const float*)d_in[2];
    const int*   rows = (const int*)d_in[3];
    const int*   cols = (const int*)d_in[4];
    float*       out  = (float*)d_out;

    cudaFuncSetAttribute(gemm_kernel, cudaFuncAttributeMaxDynamicSharedMemorySize,
                         SMEM_TOTAL);

    gather_kernel<<<(MT / 16) * K16S * 32 / 256, 256>>>(x, cols);
    wconv_kernel<<<(NR / 8) * K16S * 32 / 256, 256>>>(w);
    biasfill_kernel<<<((size_t)MT * FOUT / 4) / 256, 256>>>((float4*)d_out,
                                                            (const float4*)bias);
    gemm_kernel<<<dim3(NR / BN, MT / BM), THREADS, SMEM_TOTAL>>>(bias, rows, out);
}